// round 4
// baseline (speedup 1.0000x reference)
#include <cuda_runtime.h>
#include <cuda_bf16.h>

// Problem constants
#define BATCH 8
#define CI    64
#define CO    128
#define HH    128
#define WW    128
#define HW    (HH*WW)          // 16384

// Scratch: y = conv1x1(x), PIXEL-MAJOR layout: y[b][p][c]. 64 MiB fp32.
__device__ float g_y[BATCH * HW * CO];

// ---- tf32 helpers -----------------------------------------------------------
__device__ __forceinline__ unsigned int f2tf32(float f) {
    unsigned int u;
    asm("cvt.rna.tf32.f32 %0, %1;" : "=r"(u) : "f"(f));
    return u;
}

#define MMA_TF32(d, a, b0, b1)                                                  \
    asm volatile("mma.sync.aligned.m16n8k8.row.col.f32.tf32.tf32.f32 "          \
                 "{%0,%1,%2,%3}, {%4,%5,%6,%7}, {%8,%9}, {%0,%1,%2,%3};"        \
                 : "+f"((d)[0]), "+f"((d)[1]), "+f"((d)[2]), "+f"((d)[3])       \
                 : "r"((a)[0]), "r"((a)[1]), "r"((a)[2]), "r"((a)[3]),          \
                   "r"(b0), "r"(b1))

// ---------------------------------------------------------------------------
// Kernel 1: 1x1 conv as a 3xTF32 tensor-core GEMM.
// Per CTA (256 thr = 8 warps): 128 pixels x 128 channels, K=64.
// X and W split into tf32 hi/lo in smem (padded stride 132 for bank-freedom).
// Warp tile: 32 px x 64 ch = 2 m16-tiles x 8 n8-tiles.
// D = Ah*Bh + Ah*Bl + Al*Bh  (fp32-equivalent accuracy).
// Epilogue: accum -> padded smem stage -> +bias -> coalesced float4 stores.
// ---------------------------------------------------------------------------
#define KP 132   // padded row stride (floats)

__global__ void __launch_bounds__(256) conv1x1_mma(const float* __restrict__ x,
                                                   const float* __restrict__ Wc,
                                                   const float* __restrict__ bc)
{
    extern __shared__ float sm[];
    unsigned int* XH = reinterpret_cast<unsigned int*>(sm);            // [64][KP]
    unsigned int* XL = XH + 64 * KP;
    unsigned int* WH = XL + 64 * KP;
    unsigned int* WL = WH + 64 * KP;
    float* stage = sm;                 // reuse XH+XL region: 128*KP floats

    __shared__ float bs[CO];

    const int b   = blockIdx.y;
    const int p0  = blockIdx.x * 128;
    const int tid = threadIdx.x;

    if (tid < CO) bs[tid] = bc[tid];

    // Fill W hi/lo: WH[k][c] = tf32(Wc[c][k])
    for (int idx = tid; idx < CO * CI; idx += 256) {
        int c = idx >> 6;
        int k = idx & 63;
        float v = Wc[idx];                       // Wc[c*64+k]
        unsigned int h = f2tf32(v);
        float r = v - __uint_as_float(h);
        WH[k * KP + c] = h;
        WL[k * KP + c] = f2tf32(r);
    }
    // Fill X hi/lo: XH[k][p] = tf32(x[b][k][p0+p])
    for (int idx = tid; idx < CI * 128; idx += 256) {
        int k = idx >> 7;
        int p = idx & 127;
        float v = x[(size_t)b * CI * HW + (size_t)k * HW + p0 + p];
        unsigned int h = f2tf32(v);
        float r = v - __uint_as_float(h);
        XH[k * KP + p] = h;
        XL[k * KP + p] = f2tf32(r);
    }
    __syncthreads();

    const int warp = tid >> 5;
    const int lane = tid & 31;
    const int px0  = (warp & 3) * 32;   // 4 pixel tiles of 32
    const int ch0  = (warp >> 2) * 64;  // 2 channel tiles of 64
    const int g    = lane >> 2;
    const int tg   = lane & 3;

    float acc[2][8][4];
#pragma unroll
    for (int mt = 0; mt < 2; ++mt)
#pragma unroll
        for (int nt = 0; nt < 8; ++nt)
#pragma unroll
            for (int e = 0; e < 4; ++e) acc[mt][nt][e] = 0.0f;

#pragma unroll
    for (int ks = 0; ks < 8; ++ks) {
        const int k0 = ks * 8;

        unsigned int ah[2][4], al[2][4];
#pragma unroll
        for (int mt = 0; mt < 2; ++mt) {
            int p = px0 + mt * 16 + g;
            ah[mt][0] = XH[(k0 + tg) * KP + p];
            ah[mt][1] = XH[(k0 + tg) * KP + p + 8];
            ah[mt][2] = XH[(k0 + tg + 4) * KP + p];
            ah[mt][3] = XH[(k0 + tg + 4) * KP + p + 8];
            al[mt][0] = XL[(k0 + tg) * KP + p];
            al[mt][1] = XL[(k0 + tg) * KP + p + 8];
            al[mt][2] = XL[(k0 + tg + 4) * KP + p];
            al[mt][3] = XL[(k0 + tg + 4) * KP + p + 8];
        }

#pragma unroll
        for (int nt = 0; nt < 8; ++nt) {
            int c = ch0 + nt * 8 + g;
            unsigned int bh0 = WH[(k0 + tg) * KP + c];
            unsigned int bh1 = WH[(k0 + tg + 4) * KP + c];
            unsigned int bl0 = WL[(k0 + tg) * KP + c];
            unsigned int bl1 = WL[(k0 + tg + 4) * KP + c];
#pragma unroll
            for (int mt = 0; mt < 2; ++mt) {
                MMA_TF32(acc[mt][nt], ah[mt], bh0, bh1);
                MMA_TF32(acc[mt][nt], ah[mt], bl0, bl1);
                MMA_TF32(acc[mt][nt], al[mt], bh0, bh1);
            }
        }
    }

    __syncthreads();   // done reading X smem; reuse as stage

    // Scatter accumulators into stage[p][c] (stride KP, float2 stores)
#pragma unroll
    for (int mt = 0; mt < 2; ++mt) {
#pragma unroll
        for (int nt = 0; nt < 8; ++nt) {
            int p = px0 + mt * 16 + g;
            int c = ch0 + nt * 8 + 2 * tg;
            *reinterpret_cast<float2*>(&stage[p * KP + c]) =
                make_float2(acc[mt][nt][0], acc[mt][nt][1]);
            *reinterpret_cast<float2*>(&stage[(p + 8) * KP + c]) =
                make_float2(acc[mt][nt][2], acc[mt][nt][3]);
        }
    }
    __syncthreads();

    // Bias + coalesced float4 stores to pixel-major y
    float* yb = g_y + ((size_t)b * HW + p0) * CO;
#pragma unroll
    for (int j = 0; j < 16; ++j) {
        int fidx = tid + 256 * j;     // 0..4095 float4s
        int p  = fidx >> 5;
        int cq = fidx & 31;
        float4 v  = *reinterpret_cast<const float4*>(&stage[p * KP + cq * 4]);
        float4 bb = *reinterpret_cast<const float4*>(&bs[cq * 4]);
        v.x += bb.x; v.y += bb.y; v.z += bb.z; v.w += bb.w;
        *reinterpret_cast<float4*>(&yb[(size_t)p * CO + cq * 4]) = v;
    }
}

// ---------------------------------------------------------------------------
// Kernel 2: 3x3 local attention, warp per 1x2 pixel strip, register resident.
// CTA = 256 threads = 8 warps = 16 consecutive pixels in one image row.
// Warp loads its 3x4 neighborhood once (12 LDG.128 = 6/px), keeps it in regs
// for score pass + weighted sum.  Lane l owns channels 4l..4l+3.
// ---------------------------------------------------------------------------
__global__ void __launch_bounds__(256) attn3x3_kernel(float* __restrict__ out)
{
    __shared__ float so[16 * CO];  // [pix][c]

    const int tid  = threadIdx.x;
    const int wid  = tid >> 5;
    const int lane = tid & 31;

    const int g16 = blockIdx.x * 16;      // first pixel of CTA
    const int b   = g16 >> 14;
    const int p   = g16 & (HW - 1);
    const int h   = p >> 7;
    const int wc  = p & (WW - 1);         // CTA col start (multiple of 16)
    const int w0  = wc + wid * 2;         // warp's first pixel col

    const float* ybase = g_y + ((size_t)b * HW) * CO + lane * 4;

    // Load 3x4 neighborhood (rows h-1..h+1, cols w0-1..w0+2)
    float4 v[3][4];
#pragma unroll
    for (int r = 0; r < 3; ++r) {
        int gh = h - 1 + r;
#pragma unroll
        for (int c = 0; c < 4; ++c) {
            int gw = w0 - 1 + c;
            if ((unsigned)gh < HH && (unsigned)gw < WW) {
                v[r][c] = *reinterpret_cast<const float4*>(
                    ybase + (size_t)(gh * WW + gw) * CO);
            } else {
                v[r][c] = make_float4(0.f, 0.f, 0.f, 0.f);
            }
        }
    }

    const float scale = 0.08838834764831845f; // 1/sqrt(128)

#pragma unroll
    for (int j = 0; j < 2; ++j) {
        const float4 mid = v[1][j + 1];

        float s[9];
#pragma unroll
        for (int n = 0; n < 9; ++n) {
            const float4 q = v[n / 3][j + n % 3];
            s[n] = q.x * mid.x + q.y * mid.y + q.z * mid.z + q.w * mid.w;
        }

#pragma unroll
        for (int off = 16; off > 0; off >>= 1) {
#pragma unroll
            for (int n = 0; n < 9; ++n)
                s[n] += __shfl_xor_sync(0xffffffffu, s[n], off);
        }

        float mx = s[0];
#pragma unroll
        for (int n = 1; n < 9; ++n) mx = fmaxf(mx, s[n]);
        float a[9], den = 0.f;
#pragma unroll
        for (int n = 0; n < 9; ++n) {
            a[n] = __expf((s[n] - mx) * scale);
            den += a[n];
        }
        float inv = 1.0f / den;

        float4 o = make_float4(0.f, 0.f, 0.f, 0.f);
#pragma unroll
        for (int n = 0; n < 9; ++n) {
            const float4 q = v[n / 3][j + n % 3];
            float an = a[n] * inv;
            o.x = fmaf(an, q.x, o.x);
            o.y = fmaf(an, q.y, o.y);
            o.z = fmaf(an, q.z, o.z);
            o.w = fmaf(an, q.w, o.w);
        }

        *reinterpret_cast<float4*>(&so[(wid * 2 + j) * CO + lane * 4]) = o;
    }
    __syncthreads();

    // Transposed, channel-major store.
    {
        const int c  = tid >> 1;
        const int qb = (tid & 1) * 2;
        float* dst = out + ((size_t)b * CO + c) * HW + h * WW + wc;
#pragma unroll
        for (int j = 0; j < 2; ++j) {
            int q = qb + j;
            float4 r;
            r.x = so[(q * 4 + 0) * CO + c];
            r.y = so[(q * 4 + 1) * CO + c];
            r.z = so[(q * 4 + 2) * CO + c];
            r.w = so[(q * 4 + 3) * CO + c];
            *reinterpret_cast<float4*>(dst + q * 4) = r;
        }
    }
}

// ---------------------------------------------------------------------------
extern "C" void kernel_launch(void* const* d_in, const int* in_sizes, int n_in,
                              void* d_out, int out_size)
{
    const float* x  = nullptr;
    const float* Wc = nullptr;
    const float* bc = nullptr;
    for (int i = 0; i < n_in; ++i) {
        if (in_sizes[i] == BATCH * CI * HW) x  = (const float*)d_in[i];
        else if (in_sizes[i] == CO * CI)    Wc = (const float*)d_in[i];
        else if (in_sizes[i] == CO)         bc = (const float*)d_in[i];
    }
    float* out = (float*)d_out;

    static const int conv_smem = 4 * 64 * KP * sizeof(float);   // 135168

    cudaFuncSetAttribute(conv1x1_mma,
                         cudaFuncAttributeMaxDynamicSharedMemorySize, conv_smem);

    conv1x1_mma<<<dim3(HW / 128, BATCH), 256, conv_smem>>>(x, Wc, bc);
    attn3x3_kernel<<<BATCH * HW / 16, 256>>>(out);
}

// round 6
// speedup vs baseline: 1.0815x; 1.0815x over previous
#include <cuda_runtime.h>
#include <cuda_bf16.h>
#include <cstdint>

// Problem constants
#define BATCH 8
#define CI    64
#define CO    128
#define HH    128
#define WW    128
#define HW    (HH*WW)          // 16384

// Scratch: y = conv1x1(x), PIXEL-MAJOR layout: y[b][p][c]. 64 MiB fp32.
__device__ float g_y[BATCH * HW * CO];

// ---- bf16 split helper ------------------------------------------------------
__device__ __forceinline__ void split_bf16(float v, uint32_t& hi, uint32_t& lo) {
    __nv_bfloat16 h = __float2bfloat16_rn(v);
    float r = v - __bfloat162float(h);
    __nv_bfloat16 l = __float2bfloat16_rn(r);
    hi = (uint32_t)__bfloat16_as_ushort(h);
    lo = (uint32_t)__bfloat16_as_ushort(l);
}

#define MMA_BF16(d, a, b0, b1)                                                  \
    asm volatile("mma.sync.aligned.m16n8k16.row.col.f32.bf16.bf16.f32 "         \
                 "{%0,%1,%2,%3}, {%4,%5,%6,%7}, {%8,%9}, {%0,%1,%2,%3};"        \
                 : "+f"((d)[0]), "+f"((d)[1]), "+f"((d)[2]), "+f"((d)[3])       \
                 : "r"((a)[0]), "r"((a)[1]), "r"((a)[2]), "r"((a)[3]),          \
                   "r"(b0), "r"(b1))

// ---------------------------------------------------------------------------
// Kernel 1: 1x1 conv as a 3-term bf16-split tensor-core GEMM (m16n8k16).
// Per CTA (256 thr = 8 warps): D[128 px x 128 ch] = X[128x64] * W^T.
// Smem: X[p][kpair] and W[c][kpair] as uint2 {hi,lo} (stride 33 to de-bank).
// Warp tile: 32 px (2 x m16) x 64 ch (8 x n8); 4 k16 steps; 3 MMAs per
// (mt,nt,ks): xh*Wh + xh*Wl + xl*Wh.
// Epilogue: acc -> padded smem stage (reuses operand smem) -> +bias ->
// coalesced float4 stores to pixel-major y.
// ---------------------------------------------------------------------------
#define XW_STRIDE 33          // uint2 elements per row (32 kpairs + 1 pad)
#define KP 132                // stage stride (floats)
#define DYN_SMEM (2 * 128 * XW_STRIDE * 8)   // 67584 bytes

__global__ void __launch_bounds__(256) conv1x1_mma(const float* __restrict__ x,
                                                   const float* __restrict__ Wc,
                                                   const float* __restrict__ bc)
{
    extern __shared__ char smraw[];
    uint2* Xs = reinterpret_cast<uint2*>(smraw);                 // [128][33]
    uint2* Ws = Xs + 128 * XW_STRIDE;                            // [128][33]
    float* stage = reinterpret_cast<float*>(smraw);              // alias, epilogue

    __shared__ float bs[CO];

    const int b   = blockIdx.y;
    const int p0  = blockIdx.x * 128;
    const int tid = threadIdx.x;

    if (tid < CO) bs[tid] = bc[tid];

    // Fill X: Xs[p][kk] = {bf16hi, bf16lo} of x[b][2kk..2kk+1][p0+p] (packed k-pairs)
    {
        const float* xb = x + (size_t)b * CI * HW + p0;
        for (int idx = tid; idx < 4096; idx += 256) {
            int kk = idx >> 7;
            int p  = idx & 127;
            float v0 = xb[(size_t)(2 * kk) * HW + p];
            float v1 = xb[(size_t)(2 * kk + 1) * HW + p];
            uint32_t h0, l0, h1, l1;
            split_bf16(v0, h0, l0);
            split_bf16(v1, h1, l1);
            Xs[p * XW_STRIDE + kk] = make_uint2(h0 | (h1 << 16), l0 | (l1 << 16));
        }
    }
    // Fill W: Ws[c][kk] = {hi,lo} of Wc[c][2kk..2kk+1]
    for (int idx = tid; idx < 4096; idx += 256) {
        int c  = idx >> 5;
        int kk = idx & 31;
        float2 w = *reinterpret_cast<const float2*>(&Wc[c * CI + 2 * kk]);
        uint32_t h0, l0, h1, l1;
        split_bf16(w.x, h0, l0);
        split_bf16(w.y, h1, l1);
        Ws[c * XW_STRIDE + kk] = make_uint2(h0 | (h1 << 16), l0 | (l1 << 16));
    }
    __syncthreads();

    const int warp = tid >> 5;
    const int lane = tid & 31;
    const int px0  = (warp & 3) * 32;   // 4 pixel quarters
    const int ch0  = (warp >> 2) * 64;  // 2 channel halves
    const int g    = lane >> 2;
    const int t    = lane & 3;

    float acc[2][8][4];
#pragma unroll
    for (int mt = 0; mt < 2; ++mt)
#pragma unroll
        for (int nt = 0; nt < 8; ++nt)
#pragma unroll
            for (int e = 0; e < 4; ++e) acc[mt][nt][e] = 0.0f;

#pragma unroll
    for (int ks = 0; ks < 4; ++ks) {
        const int kp0 = ks * 8;

        // A fragments (X): a0=[g][2t..], a1=[g+8][..], a2=[g][2t+8..], a3=[g+8][..]
        uint32_t ah[2][4], al[2][4];
#pragma unroll
        for (int mt = 0; mt < 2; ++mt) {
            const int r0 = px0 + mt * 16 + g;
            uint2 A0 = Xs[r0 * XW_STRIDE + kp0 + t];
            uint2 A1 = Xs[(r0 + 8) * XW_STRIDE + kp0 + t];
            uint2 A2 = Xs[r0 * XW_STRIDE + kp0 + 4 + t];
            uint2 A3 = Xs[(r0 + 8) * XW_STRIDE + kp0 + 4 + t];
            ah[mt][0] = A0.x; ah[mt][1] = A1.x; ah[mt][2] = A2.x; ah[mt][3] = A3.x;
            al[mt][0] = A0.y; al[mt][1] = A1.y; al[mt][2] = A2.y; al[mt][3] = A3.y;
        }

#pragma unroll
        for (int nt = 0; nt < 8; ++nt) {
            const int c = ch0 + nt * 8 + g;
            uint2 B0 = Ws[c * XW_STRIDE + kp0 + t];       // b0 = W[c][2t..2t+1]
            uint2 B1 = Ws[c * XW_STRIDE + kp0 + 4 + t];   // b1 = W[c][2t+8..]
#pragma unroll
            for (int mt = 0; mt < 2; ++mt) {
                MMA_BF16(acc[mt][nt], ah[mt], B0.x, B1.x);  // xh * Wh
                MMA_BF16(acc[mt][nt], ah[mt], B0.y, B1.y);  // xh * Wl
                MMA_BF16(acc[mt][nt], al[mt], B0.x, B1.x);  // xl * Wh
            }
        }
    }

    __syncthreads();   // operand smem fully consumed; reuse as stage

    // Scatter accumulators into stage[p][c] (stride KP, float2 stores)
#pragma unroll
    for (int mt = 0; mt < 2; ++mt) {
#pragma unroll
        for (int nt = 0; nt < 8; ++nt) {
            int p = px0 + mt * 16 + g;
            int c = ch0 + nt * 8 + 2 * t;
            *reinterpret_cast<float2*>(&stage[p * KP + c]) =
                make_float2(acc[mt][nt][0], acc[mt][nt][1]);
            *reinterpret_cast<float2*>(&stage[(p + 8) * KP + c]) =
                make_float2(acc[mt][nt][2], acc[mt][nt][3]);
        }
    }
    __syncthreads();

    // Bias + coalesced float4 stores to pixel-major y
    float* yb = g_y + ((size_t)b * HW + p0) * CO;
#pragma unroll
    for (int j = 0; j < 16; ++j) {
        int fidx = tid + 256 * j;     // 0..4095 float4s
        int p  = fidx >> 5;
        int cq = fidx & 31;
        float4 v  = *reinterpret_cast<const float4*>(&stage[p * KP + cq * 4]);
        float4 bb = *reinterpret_cast<const float4*>(&bs[cq * 4]);
        v.x += bb.x; v.y += bb.y; v.z += bb.z; v.w += bb.w;
        *reinterpret_cast<float4*>(&yb[(size_t)p * CO + cq * 4]) = v;
    }
}

// ---------------------------------------------------------------------------
// Kernel 2: 3x3 local attention, warp per 1x2 pixel strip, register resident.
// (best-known variant, unchanged)
// ---------------------------------------------------------------------------
__global__ void __launch_bounds__(256) attn3x3_kernel(float* __restrict__ out)
{
    __shared__ float so[16 * CO];  // [pix][c]

    const int tid  = threadIdx.x;
    const int wid  = tid >> 5;
    const int lane = tid & 31;

    const int g16 = blockIdx.x * 16;
    const int b   = g16 >> 14;
    const int p   = g16 & (HW - 1);
    const int h   = p >> 7;
    const int wc  = p & (WW - 1);
    const int w0  = wc + wid * 2;

    const float* ybase = g_y + ((size_t)b * HW) * CO + lane * 4;

    float4 v[3][4];
#pragma unroll
    for (int r = 0; r < 3; ++r) {
        int gh = h - 1 + r;
#pragma unroll
        for (int c = 0; c < 4; ++c) {
            int gw = w0 - 1 + c;
            if ((unsigned)gh < HH && (unsigned)gw < WW) {
                v[r][c] = *reinterpret_cast<const float4*>(
                    ybase + (size_t)(gh * WW + gw) * CO);
            } else {
                v[r][c] = make_float4(0.f, 0.f, 0.f, 0.f);
            }
        }
    }

    const float scale = 0.08838834764831845f; // 1/sqrt(128)

#pragma unroll
    for (int j = 0; j < 2; ++j) {
        const float4 mid = v[1][j + 1];

        float s[9];
#pragma unroll
        for (int n = 0; n < 9; ++n) {
            const float4 q = v[n / 3][j + n % 3];
            s[n] = q.x * mid.x + q.y * mid.y + q.z * mid.z + q.w * mid.w;
        }

#pragma unroll
        for (int off = 16; off > 0; off >>= 1) {
#pragma unroll
            for (int n = 0; n < 9; ++n)
                s[n] += __shfl_xor_sync(0xffffffffu, s[n], off);
        }

        float mx = s[0];
#pragma unroll
        for (int n = 1; n < 9; ++n) mx = fmaxf(mx, s[n]);
        float a[9], den = 0.f;
#pragma unroll
        for (int n = 0; n < 9; ++n) {
            a[n] = __expf((s[n] - mx) * scale);
            den += a[n];
        }
        float inv = 1.0f / den;

        float4 o = make_float4(0.f, 0.f, 0.f, 0.f);
#pragma unroll
        for (int n = 0; n < 9; ++n) {
            const float4 q = v[n / 3][j + n % 3];
            float an = a[n] * inv;
            o.x = fmaf(an, q.x, o.x);
            o.y = fmaf(an, q.y, o.y);
            o.z = fmaf(an, q.z, o.z);
            o.w = fmaf(an, q.w, o.w);
        }

        *reinterpret_cast<float4*>(&so[(wid * 2 + j) * CO + lane * 4]) = o;
    }
    __syncthreads();

    {
        const int c  = tid >> 1;
        const int qb = (tid & 1) * 2;
        float* dst = out + ((size_t)b * CO + c) * HW + h * WW + wc;
#pragma unroll
        for (int j = 0; j < 2; ++j) {
            int q = qb + j;
            float4 r;
            r.x = so[(q * 4 + 0) * CO + c];
            r.y = so[(q * 4 + 1) * CO + c];
            r.z = so[(q * 4 + 2) * CO + c];
            r.w = so[(q * 4 + 3) * CO + c];
            *reinterpret_cast<float4*>(dst + q * 4) = r;
        }
    }
}

// ---------------------------------------------------------------------------
extern "C" void kernel_launch(void* const* d_in, const int* in_sizes, int n_in,
                              void* d_out, int out_size)
{
    const float* x  = nullptr;
    const float* Wc = nullptr;
    const float* bc = nullptr;
    for (int i = 0; i < n_in; ++i) {
        if (in_sizes[i] == BATCH * CI * HW) x  = (const float*)d_in[i];
        else if (in_sizes[i] == CO * CI)    Wc = (const float*)d_in[i];
        else if (in_sizes[i] == CO)         bc = (const float*)d_in[i];
    }
    float* out = (float*)d_out;

    cudaFuncSetAttribute(conv1x1_mma,
                         cudaFuncAttributeMaxDynamicSharedMemorySize, DYN_SMEM);

    conv1x1_mma<<<dim3(HW / 128, BATCH), 256, DYN_SMEM>>>(x, Wc, bc);
    attn3x3_kernel<<<BATCH * HW / 16, 256>>>(out);
}